// round 11
// baseline (speedup 1.0000x reference)
#include <cuda_runtime.h>
#include <cuda_bf16.h>
#include <cstdint>
#include <cstddef>

typedef __nv_bfloat16 bf16;

#define TOK    100352     // B * H * W
#define NWIN   2048       // B * 64 windows

// ---------------- scratch (static device memory; no allocs) ----------------
__device__ bf16  g_hw  [(size_t)TOK * 128];        // LN1+shift+partition output (window order)
__device__ bf16  g_q   [(size_t)NWIN * 4 * 49 * 32];
__device__ bf16  g_k   [(size_t)NWIN * 4 * 49 * 32];
__device__ bf16  g_v   [(size_t)NWIN * 4 * 49 * 32];
__device__ bf16  g_o   [(size_t)TOK * 128];        // attention output (window order)
__device__ float g_x1  [(size_t)TOK * 128];        // after proj + residual (image order)
__device__ bf16  g_t   [(size_t)TOK * 128];        // LN2 output
__device__ bf16  g_h   [(size_t)TOK * 512];        // fc1+gelu output
__device__ bf16  g_wqkv[384 * 128];                // Bt layouts: [n][k]
__device__ bf16  g_wproj[128 * 128];
__device__ bf16  g_wfc1 [512 * 128];
__device__ bf16  g_wfc2 [128 * 512];
__device__ float4 g_bm4[229376];                   // bias+mask in C-fragment layout

// ---------------- helpers ----------------
__device__ __forceinline__ void mma16816(float c[4], const uint32_t a[4], const uint32_t b[2]) {
    asm volatile(
        "mma.sync.aligned.m16n8k16.row.col.f32.bf16.bf16.f32 "
        "{%0,%1,%2,%3}, {%4,%5,%6,%7}, {%8,%9}, {%0,%1,%2,%3};\n"
        : "+f"(c[0]), "+f"(c[1]), "+f"(c[2]), "+f"(c[3])
        : "r"(a[0]), "r"(a[1]), "r"(a[2]), "r"(a[3]), "r"(b[0]), "r"(b[1]));
}
__device__ __forceinline__ void ldsm4(uint32_t& r0, uint32_t& r1, uint32_t& r2, uint32_t& r3,
                                      const void* p) {
    uint32_t addr = (uint32_t)__cvta_generic_to_shared(p);
    asm volatile("ldmatrix.sync.aligned.m8n8.x4.shared.b16 {%0,%1,%2,%3}, [%4];\n"
                 : "=r"(r0), "=r"(r1), "=r"(r2), "=r"(r3) : "r"(addr));
}
__device__ __forceinline__ void cpasync16(void* smem_dst, const void* gsrc) {
    uint32_t da = (uint32_t)__cvta_generic_to_shared(smem_dst);
    asm volatile("cp.async.cg.shared.global [%0], [%1], 16;\n" :: "r"(da), "l"(gsrc));
}

// ---------------- prep: weight transpose -> bf16, fragment-layout bias+mask ----------------
__global__ void prep_k(const float* __restrict__ qkv_w, const float* __restrict__ proj_w,
                       const float* __restrict__ fc1_w, const float* __restrict__ fc2_w,
                       const float* __restrict__ rpb,
                       bf16* __restrict__ wq, bf16* __restrict__ wp,
                       bf16* __restrict__ w1, bf16* __restrict__ w2,
                       float* __restrict__ bm4) {
    int m = blockIdx.x * 256 + threadIdx.x;
    if (m < 49152) { int n = m >> 7, k = m & 127; wq[m] = __float2bfloat16(qkv_w[k * 384 + n]); return; }
    m -= 49152;
    if (m < 16384) { int n = m >> 7, k = m & 127; wp[m] = __float2bfloat16(proj_w[k * 128 + n]); return; }
    m -= 16384;
    if (m < 65536) { int n = m >> 7, k = m & 127; w1[m] = __float2bfloat16(fc1_w[k * 512 + n]); return; }
    m -= 65536;
    if (m < 65536) { int n = m >> 9, k = m & 511; w2[m] = __float2bfloat16(fc2_w[k * 128 + n]); return; }
    m -= 65536;
    if (m < 917504) {
        int e = m & 3, lane = (m >> 2) & 31;
        int t = m >> 7;
        int nt = t % 7, q = t / 7;
        int warp = q & 3, hw = q >> 2;
        int head = hw >> 6, w = hw & 63;
        int r = warp * 16 + (lane >> 2) + (e >> 1) * 8;
        int c = nt * 8 + (lane & 3) * 2 + (e & 1);
        float val = -1e30f;
        if (r < 49 && c < 49) {
            int d0 = r / 7 - c / 7 + 6, d1 = r % 7 - c % 7 + 6;
            float bias = rpb[(d0 * 13 + d1) * 4 + head];
            int hi = (w >> 3) * 7 + r / 7, wi = (w & 7) * 7 + r % 7;
            int hj = (w >> 3) * 7 + c / 7, wj = (w & 7) * 7 + c % 7;
            int ri = (hi < 49 ? 0 : (hi < 53 ? 1 : 2)) * 3 + (wi < 49 ? 0 : (wi < 53 ? 1 : 2));
            int rj = (hj < 49 ? 0 : (hj < 53 ? 1 : 2)) * 3 + (wj < 49 ? 0 : (wj < 53 ? 1 : 2));
            val = bias + ((ri != rj) ? -100.0f : 0.0f);
        }
        bm4[m] = val;
    }
}

// ---------------- LayerNorm (optionally with shift+window-partition gather) ----------------
template <bool SHIFTMAP>
__global__ __launch_bounds__(256) void ln_k(const float* __restrict__ X, const float* __restrict__ G,
                                            const float* __restrict__ Bv, bf16* __restrict__ OUT) {
    int gw = (blockIdx.x * 256 + threadIdx.x) >> 5;
    int lane = threadIdx.x & 31;
    if (gw >= TOK) return;
    size_t src;
    if (SHIFTMAP) {
        int bimg = gw / 3136, rem = gw - bimg * 3136;
        int wi = rem / 49, n = rem - wi * 49;
        int sh = (wi >> 3) * 7 + n / 7, sw = (wi & 7) * 7 + n % 7;
        int oh = sh + 3; if (oh >= 56) oh -= 56;
        int ow = sw + 3; if (ow >= 56) ow -= 56;
        src = ((size_t)bimg * 3136 + oh * 56 + ow) * 128;
    } else {
        src = (size_t)gw * 128;
    }
    float4 v = *(const float4*)&X[src + lane * 4];
    float s = v.x + v.y + v.z + v.w;
    float sq = v.x * v.x + v.y * v.y + v.z * v.z + v.w * v.w;
#pragma unroll
    for (int i = 16; i; i >>= 1) {
        s  += __shfl_xor_sync(0xffffffffu, s, i);
        sq += __shfl_xor_sync(0xffffffffu, sq, i);
    }
    float mean = s * 0.0078125f;
    float var = sq * 0.0078125f - mean * mean;
    float rstd = rsqrtf(var + 1e-5f);
    float4 gg = *(const float4*)&G[lane * 4];
    float4 bb = *(const float4*)&Bv[lane * 4];
    float y0 = (v.x - mean) * rstd * gg.x + bb.x;
    float y1 = (v.y - mean) * rstd * gg.y + bb.y;
    float y2 = (v.z - mean) * rstd * gg.z + bb.z;
    float y3 = (v.w - mean) * rstd * gg.w + bb.w;
    __nv_bfloat162* dst = (__nv_bfloat162*)(OUT + (size_t)gw * 128);
    dst[lane * 2]     = __floats2bfloat162_rn(y0, y1);
    dst[lane * 2 + 1] = __floats2bfloat162_rn(y2, y3);
}

// ---------------- GEMM epilogues ----------------
// MODE 0: QKV scatter  1: proj+merge+reverse-shift+residual  2: fc1+GELU  3: fc2+residual
template <int MODE>
__device__ __forceinline__ void epi(int row, int col, float v,
                                    const float* __restrict__ bias, float* __restrict__ outF,
                                    bf16* __restrict__ o1, bf16* __restrict__ o2, bf16* __restrict__ o3,
                                    const float* __restrict__ resid) {
    v += bias[col];
    if (MODE == 0) {
        int three = col >> 7, hc = col & 127, head = hc >> 5, d = hc & 31;
        int win = row / 49, n = row - win * 49;
        size_t idx = ((size_t)(win * 4 + head) * 49 + n) * 32 + d;
        if (three == 0)      o1[idx] = __float2bfloat16(v * 0.17677669529663687f);
        else if (three == 1) o2[idx] = __float2bfloat16(v);
        else                 o3[idx] = __float2bfloat16(v);
    } else if (MODE == 1) {
        int bimg = row / 3136, rem = row - bimg * 3136;
        int wi = rem / 49, n = rem - wi * 49;
        int sh = (wi >> 3) * 7 + n / 7, sw = (wi & 7) * 7 + n % 7;
        int fh = sh + 3; if (fh >= 56) fh -= 56;
        int fw = sw + 3; if (fw >= 56) fw -= 56;
        size_t idx = ((size_t)bimg * 3136 + fh * 56 + fw) * 128 + col;
        outF[idx] = resid[idx] + v;
    } else if (MODE == 2) {
        float gl = 0.5f * v * (1.0f + erff(v * 0.70710678118654752f));
        o1[(size_t)row * 512 + col] = __float2bfloat16(gl);
    } else {
        size_t idx = (size_t)row * 128 + col;
        outF[idx] = resid[idx] + v;
    }
}

// ---------------- A-resident GEMM: K=128, A row-block cached in smem, loop over NGY N-blocks --
// A[128][136] resident; B double-buffered k64 chunks, single __syncthreads per chunk.
template <int NGY, int MODE>
__global__ __launch_bounds__(256, 2) void gemm_ar(const bf16* __restrict__ A, const bf16* __restrict__ Bt,
                                                  const float* __restrict__ bias,
                                                  float* __restrict__ outF,
                                                  bf16* __restrict__ o1, bf16* __restrict__ o2, bf16* __restrict__ o3,
                                                  const float* __restrict__ resid) {
    extern __shared__ __align__(16) bf16 sm[];
    bf16* Asm = sm;                       // 128 * 136
    bf16* Bsm = sm + 128 * 136;           // 2 * 128 * 72
    const int tid = threadIdx.x;
    const int warp = tid >> 5, lane = tid & 31;
    const int wm = warp & 1, wn = warp >> 1;
    const int g = lane >> 2, t4 = lane & 3;
    const int bm0 = blockIdx.x * 128;
    const int lrow = lane & 15, lcol = (lane >> 4) << 3;

    // ---- issue A loads (2048 16B chunks, 8/thread) ----
#pragma unroll
    for (int it = 0; it < 8; ++it) {
        int idx = tid + it * 256;
        int r = idx >> 4, q = (idx & 15) * 8;
        cpasync16(&Asm[r * 136 + q], &A[(size_t)(bm0 + r) * 128 + q]);
    }
    // ---- B chunk loader: chunk t covers Bt rows (t>>1)*128.., cols (t&1)*64.. ----
#define LOADB(t)                                                                              \
    do {                                                                                      \
        _Pragma("unroll")                                                                     \
        for (int it = 0; it < 4; ++it) {                                                      \
            int idx = tid + it * 256;                                                         \
            int r = idx >> 3, q = (idx & 7) * 8;                                              \
            cpasync16(&Bsm[((t) & 1) * 9216 + r * 72 + q],                                    \
                      &Bt[(size_t)(((t) >> 1) * 128 + r) * 128 + ((t) & 1) * 64 + q]);        \
        }                                                                                     \
        asm volatile("cp.async.commit_group;\n");                                             \
    } while (0)

    LOADB(0);   // group 0 = A + B0

    float acc[4][4][4];
    constexpr int TC = NGY * 2;
#pragma unroll 1
    for (int t = 0; t < TC; ++t) {
        if (t + 1 < TC) {
            LOADB(t + 1);
            asm volatile("cp.async.wait_group 1;\n");
        } else {
            asm volatile("cp.async.wait_group 0;\n");
        }
        __syncthreads();

        const int ch = t & 1;
        if (ch == 0) {
#pragma unroll
            for (int a = 0; a < 4; a++)
#pragma unroll
                for (int b = 0; b < 4; b++)
#pragma unroll
                    for (int c = 0; c < 4; c++) acc[a][b][c] = 0.0f;
        }
        const bf16* Bs = Bsm + (t & 1) * 9216;
#pragma unroll
        for (int ks = 0; ks < 4; ++ks) {
            const int ka = ch * 64 + ks * 16;   // A column
            const int kb = ks * 16;             // B column (within chunk)
            uint32_t af[4][4];
#pragma unroll
            for (int mt = 0; mt < 4; ++mt) {
                int m0 = wm * 64 + mt * 16;
                ldsm4(af[mt][0], af[mt][1], af[mt][2], af[mt][3],
                      &Asm[(m0 + lrow) * 136 + ka + lcol]);
            }
            uint32_t bfr[4][2];
#pragma unroll
            for (int np = 0; np < 2; ++np) {
                int n0 = wn * 32 + np * 16;
                uint32_t r0, r1, r2, r3;
                ldsm4(r0, r1, r2, r3, &Bs[(n0 + lrow) * 72 + kb + lcol]);
                bfr[np * 2][0] = r0; bfr[np * 2 + 1][0] = r1;
                bfr[np * 2][1] = r2; bfr[np * 2 + 1][1] = r3;
            }
#pragma unroll
            for (int mt = 0; mt < 4; ++mt)
#pragma unroll
                for (int nt = 0; nt < 4; ++nt)
                    mma16816(acc[mt][nt], af[mt], bfr[nt]);
        }

        if (ch == 1) {
            const int bn0 = (t >> 1) * 128;
#pragma unroll
            for (int mt = 0; mt < 4; ++mt) {
#pragma unroll
                for (int nt = 0; nt < 4; ++nt) {
                    int row0 = bm0 + wm * 64 + mt * 16 + g;
                    int col0 = bn0 + wn * 32 + nt * 8 + 2 * t4;
                    epi<MODE>(row0,     col0,     acc[mt][nt][0], bias, outF, o1, o2, o3, resid);
                    epi<MODE>(row0,     col0 + 1, acc[mt][nt][1], bias, outF, o1, o2, o3, resid);
                    epi<MODE>(row0 + 8, col0,     acc[mt][nt][2], bias, outF, o1, o2, o3, resid);
                    epi<MODE>(row0 + 8, col0 + 1, acc[mt][nt][3], bias, outF, o1, o2, o3, resid);
                }
            }
        }
        if (t + 1 < TC) __syncthreads();
    }
#undef LOADB
}

// ---------------- streaming GEMM (fc2, K=512): 128x128 tile, k64 chunks, 2-stage ------------
template <int KTOT, int MODE>
__global__ __launch_bounds__(256, 2) void gemm_k(const bf16* __restrict__ A, const bf16* __restrict__ Bt,
                                                 const float* __restrict__ bias,
                                                 float* __restrict__ outF,
                                                 bf16* __restrict__ o1, bf16* __restrict__ o2, bf16* __restrict__ o3,
                                                 const float* __restrict__ resid) {
    extern __shared__ __align__(16) bf16 sm[];
    bf16* Asm = sm;                    // 2*128*72
    bf16* Bsm = sm + 2 * 128 * 72;
    const int tid = threadIdx.x;
    const int warp = tid >> 5, lane = tid & 31;
    const int wm = warp & 1, wn = warp >> 1;
    const int g = lane >> 2, t4 = lane & 3;
    const int bm0 = blockIdx.x * 128, bn0 = blockIdx.y * 128;
    const int lrow = lane & 15, lcol = (lane >> 4) << 3;

    float acc[4][4][4];
#pragma unroll
    for (int a = 0; a < 4; a++)
#pragma unroll
        for (int b = 0; b < 4; b++)
#pragma unroll
            for (int c = 0; c < 4; c++) acc[a][b][c] = 0.0f;

#define LOAD_STAGE(st, kk)                                                                    \
    do {                                                                                      \
        _Pragma("unroll")                                                                     \
        for (int it = 0; it < 4; ++it) {                                                      \
            int idx = tid + it * 256;                                                         \
            int r = idx >> 3, q = (idx & 7) * 8;                                              \
            cpasync16(&Asm[(st) * 9216 + r * 72 + q], &A[(size_t)(bm0 + r) * KTOT + (kk) + q]);  \
            cpasync16(&Bsm[(st) * 9216 + r * 72 + q], &Bt[(size_t)(bn0 + r) * KTOT + (kk) + q]); \
        }                                                                                     \
        asm volatile("cp.async.commit_group;\n");                                             \
    } while (0)

    constexpr int NCH = KTOT / 64;
    LOAD_STAGE(0, 0);
#pragma unroll
    for (int i = 0; i < NCH; ++i) {
        if (i + 1 < NCH) {
            LOAD_STAGE((i + 1) & 1, (i + 1) * 64);
            asm volatile("cp.async.wait_group 1;\n");
        } else {
            asm volatile("cp.async.wait_group 0;\n");
        }
        __syncthreads();
        const bf16* As = Asm + (i & 1) * 9216;
        const bf16* Bs = Bsm + (i & 1) * 9216;
#pragma unroll
        for (int ks = 0; ks < 4; ++ks) {
            const int k0 = ks * 16;
            uint32_t af[4][4];
#pragma unroll
            for (int mt = 0; mt < 4; ++mt) {
                int m0 = wm * 64 + mt * 16;
                ldsm4(af[mt][0], af[mt][1], af[mt][2], af[mt][3],
                      &As[(m0 + lrow) * 72 + k0 + lcol]);
            }
            uint32_t bfr[4][2];
#pragma unroll
            for (int np = 0; np < 2; ++np) {
                int n0 = wn * 32 + np * 16;
                uint32_t r0, r1, r2, r3;
                ldsm4(r0, r1, r2, r3, &Bs[(n0 + lrow) * 72 + k0 + lcol]);
                bfr[np * 2][0] = r0; bfr[np * 2 + 1][0] = r1;
                bfr[np * 2][1] = r2; bfr[np * 2 + 1][1] = r3;
            }
#pragma unroll
            for (int mt = 0; mt < 4; ++mt)
#pragma unroll
                for (int nt = 0; nt < 4; ++nt)
                    mma16816(acc[mt][nt], af[mt], bfr[nt]);
        }
        __syncthreads();
    }
#undef LOAD_STAGE
#pragma unroll
    for (int mt = 0; mt < 4; ++mt) {
#pragma unroll
        for (int nt = 0; nt < 4; ++nt) {
            int row0 = bm0 + wm * 64 + mt * 16 + g;
            int col0 = bn0 + wn * 32 + nt * 8 + 2 * t4;
            epi<MODE>(row0,     col0,     acc[mt][nt][0], bias, outF, o1, o2, o3, resid);
            epi<MODE>(row0,     col0 + 1, acc[mt][nt][1], bias, outF, o1, o2, o3, resid);
            epi<MODE>(row0 + 8, col0,     acc[mt][nt][2], bias, outF, o1, o2, o3, resid);
            epi<MODE>(row0 + 8, col0 + 1, acc[mt][nt][3], bias, outF, o1, o2, o3, resid);
        }
    }
}

// ---------------- attention: one block per (window, head), register softmax ----------------
__global__ __launch_bounds__(128) void attn_k(const bf16* __restrict__ Q, const bf16* __restrict__ K,
                                              const bf16* __restrict__ V,
                                              const float4* __restrict__ bm4,
                                              bf16* __restrict__ O) {
    __shared__ bf16 qs[64][36];
    __shared__ bf16 ksm[56][36];
    __shared__ bf16 vts[32][72];   // V transposed: [d][j], cols 49..63 zero

    const int tid = threadIdx.x, warp = tid >> 5, lane = tid & 31;
    const int g = lane >> 2, t4 = lane & 3;
    const int bx = blockIdx.x, win = bx >> 2, head = bx & 3, wimg = win & 63;
    const bf16* qg = Q + (size_t)bx * 1568;
    const bf16* kg = K + (size_t)bx * 1568;
    const bf16* vg = V + (size_t)bx * 1568;

    const float4* bmq = bm4 + (size_t)(((head * 64 + wimg) * 4 + warp) * 7) * 32;
    float4 bmv[7];
#pragma unroll
    for (int nt = 0; nt < 7; nt++) bmv[nt] = __ldg(&bmq[nt * 32 + lane]);

    for (int i = tid; i < 1024; i += 128) {
        int r = i >> 4, c = (i & 15) * 2;
        uint32_t val = (i < 784) ? *(const uint32_t*)&qg[2 * i] : 0u;
        *(uint32_t*)&qs[r][c] = val;
    }
    for (int i = tid; i < 896; i += 128) {
        int r = i >> 4, c = (i & 15) * 2;
        uint32_t val = (i < 784) ? *(const uint32_t*)&kg[2 * i] : 0u;
        *(uint32_t*)&ksm[r][c] = val;
    }
    for (int i = tid; i < 1568; i += 128) {
        int j = i >> 5, d = i & 31;
        vts[d][j] = vg[i];
    }
    for (int i = tid; i < 480; i += 128) {
        int d = i / 15, j = 49 + (i - d * 15);
        vts[d][j] = __float2bfloat16(0.0f);
    }
    __syncthreads();

    const int m0 = warp * 16;
    float sacc[7][4];
#pragma unroll
    for (int nt = 0; nt < 7; nt++) { sacc[nt][0] = sacc[nt][1] = sacc[nt][2] = sacc[nt][3] = 0.f; }
#pragma unroll
    for (int kq = 0; kq < 2; ++kq) {
        const int k0 = kq * 16;
        uint32_t af[4];
        af[0] = *(const uint32_t*)&qs[m0 + g    ][k0 + 2 * t4    ];
        af[1] = *(const uint32_t*)&qs[m0 + g + 8][k0 + 2 * t4    ];
        af[2] = *(const uint32_t*)&qs[m0 + g    ][k0 + 2 * t4 + 8];
        af[3] = *(const uint32_t*)&qs[m0 + g + 8][k0 + 2 * t4 + 8];
#pragma unroll
        for (int nt = 0; nt < 7; nt++) {
            uint32_t bb[2];
            bb[0] = *(const uint32_t*)&ksm[nt * 8 + g][k0 + 2 * t4    ];
            bb[1] = *(const uint32_t*)&ksm[nt * 8 + g][k0 + 2 * t4 + 8];
            mma16816(sacc[nt], af, bb);
        }
    }

    float l1[7][2], l2[7][2];
#pragma unroll
    for (int nt = 0; nt < 7; nt++) {
        l1[nt][0] = sacc[nt][0] + bmv[nt].x;
        l1[nt][1] = sacc[nt][1] + bmv[nt].y;
        l2[nt][0] = sacc[nt][2] + bmv[nt].z;
        l2[nt][1] = sacc[nt][3] + bmv[nt].w;
    }
    float mx1 = -1e30f, mx2 = -1e30f;
#pragma unroll
    for (int nt = 0; nt < 7; nt++) {
        mx1 = fmaxf(mx1, fmaxf(l1[nt][0], l1[nt][1]));
        mx2 = fmaxf(mx2, fmaxf(l2[nt][0], l2[nt][1]));
    }
    mx1 = fmaxf(mx1, __shfl_xor_sync(0xffffffffu, mx1, 1));
    mx1 = fmaxf(mx1, __shfl_xor_sync(0xffffffffu, mx1, 2));
    mx2 = fmaxf(mx2, __shfl_xor_sync(0xffffffffu, mx2, 1));
    mx2 = fmaxf(mx2, __shfl_xor_sync(0xffffffffu, mx2, 2));
    float sm1 = 0.f, sm2 = 0.f;
#pragma unroll
    for (int nt = 0; nt < 7; nt++) {
#pragma unroll
        for (int e = 0; e < 2; e++) {
            l1[nt][e] = __expf(l1[nt][e] - mx1);
            l2[nt][e] = __expf(l2[nt][e] - mx2);
            sm1 += l1[nt][e];
            sm2 += l2[nt][e];
        }
    }
    sm1 += __shfl_xor_sync(0xffffffffu, sm1, 1);
    sm1 += __shfl_xor_sync(0xffffffffu, sm1, 2);
    sm2 += __shfl_xor_sync(0xffffffffu, sm2, 1);
    sm2 += __shfl_xor_sync(0xffffffffu, sm2, 2);
    const float inv1 = 1.0f / sm1, inv2 = 1.0f / sm2;
    uint32_t pk1[7], pk2[7];
#pragma unroll
    for (int nt = 0; nt < 7; nt++) {
        __nv_bfloat162 p1 = __floats2bfloat162_rn(l1[nt][0] * inv1, l1[nt][1] * inv1);
        __nv_bfloat162 p2 = __floats2bfloat162_rn(l2[nt][0] * inv2, l2[nt][1] * inv2);
        pk1[nt] = *(uint32_t*)&p1;
        pk2[nt] = *(uint32_t*)&p2;
    }

    float oacc[4][4];
#pragma unroll
    for (int nt = 0; nt < 4; nt++) { oacc[nt][0] = oacc[nt][1] = oacc[nt][2] = oacc[nt][3] = 0.f; }
#pragma unroll
    for (int kt = 0; kt < 4; ++kt) {
        const int k0 = kt * 16;
        uint32_t af[4];
        af[0] = pk1[2 * kt];
        af[1] = pk2[2 * kt];
        af[2] = (kt < 3) ? pk1[2 * kt + 1] : 0u;
        af[3] = (kt < 3) ? pk2[2 * kt + 1] : 0u;
#pragma unroll
        for (int nt = 0; nt < 4; nt++) {
            uint32_t bb[2];
            bb[0] = *(const uint32_t*)&vts[nt * 8 + g][k0 + 2 * t4    ];
            bb[1] = *(const uint32_t*)&vts[nt * 8 + g][k0 + 2 * t4 + 8];
            mma16816(oacc[nt], af, bb);
        }
    }
    const size_t obase = (size_t)win * 49;
    const int r1 = m0 + g, r2 = m0 + g + 8;
#pragma unroll
    for (int nt = 0; nt < 4; nt++) {
        int col = head * 32 + nt * 8 + 2 * t4;
        if (r1 < 49)
            *(__nv_bfloat162*)&O[(obase + r1) * 128 + col] = __floats2bfloat162_rn(oacc[nt][0], oacc[nt][1]);
        if (r2 < 49)
            *(__nv_bfloat162*)&O[(obase + r2) * 128 + col] = __floats2bfloat162_rn(oacc[nt][2], oacc[nt][3]);
    }
}

// ---------------- host ----------------
extern "C" void kernel_launch(void* const* d_in, const int* in_sizes, int n_in,
                              void* d_out, int out_size) {
    const float* x      = (const float*)d_in[0];
    const float* n1g    = (const float*)d_in[1];
    const float* n1b    = (const float*)d_in[2];
    const float* qkv_w  = (const float*)d_in[3];
    const float* qkv_b  = (const float*)d_in[4];
    const float* proj_w = (const float*)d_in[5];
    const float* proj_b = (const float*)d_in[6];
    const float* rpb    = (const float*)d_in[7];
    const float* n2g    = (const float*)d_in[8];
    const float* n2b    = (const float*)d_in[9];
    const float* fc1_w  = (const float*)d_in[10];
    const float* fc1_b  = (const float*)d_in[11];
    const float* fc2_w  = (const float*)d_in[12];
    const float* fc2_b  = (const float*)d_in[13];
    float* out = (float*)d_out;

    void* p;
    cudaGetSymbolAddress(&p, g_hw);    bf16* hw = (bf16*)p;
    cudaGetSymbolAddress(&p, g_q);     bf16* qb = (bf16*)p;
    cudaGetSymbolAddress(&p, g_k);     bf16* kb = (bf16*)p;
    cudaGetSymbolAddress(&p, g_v);     bf16* vb = (bf16*)p;
    cudaGetSymbolAddress(&p, g_o);     bf16* ob = (bf16*)p;
    cudaGetSymbolAddress(&p, g_x1);    float* x1 = (float*)p;
    cudaGetSymbolAddress(&p, g_t);     bf16* tb = (bf16*)p;
    cudaGetSymbolAddress(&p, g_h);     bf16* hb = (bf16*)p;
    cudaGetSymbolAddress(&p, g_wqkv);  bf16* wq = (bf16*)p;
    cudaGetSymbolAddress(&p, g_wproj); bf16* wp = (bf16*)p;
    cudaGetSymbolAddress(&p, g_wfc1);  bf16* w1 = (bf16*)p;
    cudaGetSymbolAddress(&p, g_wfc2);  bf16* w2 = (bf16*)p;
    cudaGetSymbolAddress(&p, g_bm4);   float* bmp = (float*)p;

    const int ARSM = 128 * 136 * 2 + 2 * 128 * 72 * 2;   // 71680 bytes
    const int GSM  = 2 * 128 * 72 * 2 * 2;                // 73728 bytes
    cudaFuncSetAttribute(gemm_ar<3, 0>, cudaFuncAttributeMaxDynamicSharedMemorySize, ARSM);
    cudaFuncSetAttribute(gemm_ar<1, 1>, cudaFuncAttributeMaxDynamicSharedMemorySize, ARSM);
    cudaFuncSetAttribute(gemm_ar<4, 2>, cudaFuncAttributeMaxDynamicSharedMemorySize, ARSM);
    cudaFuncSetAttribute(gemm_k<512, 3>, cudaFuncAttributeMaxDynamicSharedMemorySize, GSM);

    prep_k<<<4352, 256>>>(qkv_w, proj_w, fc1_w, fc2_w, rpb, wq, wp, w1, w2, bmp);
    ln_k<true><<<12544, 256>>>(x, n1g, n1b, hw);
    gemm_ar<3, 0><<<784, 256, ARSM>>>(hw, wq, qkv_b, nullptr, qb, kb, vb, nullptr);
    attn_k<<<8192, 128>>>(qb, kb, vb, (const float4*)bmp, ob);
    gemm_ar<1, 1><<<784, 256, ARSM>>>(ob, wp, proj_b, x1, nullptr, nullptr, nullptr, x);
    ln_k<false><<<12544, 256>>>(x1, n2g, n2b, tb);
    gemm_ar<4, 2><<<784, 256, ARSM>>>(tb, w1, fc1_b, nullptr, hb, nullptr, nullptr, nullptr);
    gemm_k<512, 3><<<dim3(784, 1), 256, GSM>>>(hb, w2, fc2_b, out, nullptr, nullptr, nullptr, x1);
}

// round 15
// speedup vs baseline: 1.1562x; 1.1562x over previous
#include <cuda_runtime.h>
#include <cuda_bf16.h>
#include <cstdint>
#include <cstddef>

typedef __nv_bfloat16 bf16;

#define TOK    100352     // B * H * W
#define NWIN   2048       // B * 64 windows

// ---------------- scratch (static device memory; no allocs) ----------------
__device__ bf16  g_hw  [(size_t)TOK * 128];        // LN1+shift+partition output (window order)
__device__ bf16  g_q   [(size_t)NWIN * 4 * 49 * 32];
__device__ bf16  g_k   [(size_t)NWIN * 4 * 49 * 32];
__device__ bf16  g_v   [(size_t)NWIN * 4 * 49 * 32];
__device__ bf16  g_o   [(size_t)TOK * 128];        // attention output (window order)
__device__ float g_x1  [(size_t)TOK * 128];        // after proj + residual (image order)
__device__ bf16  g_t   [(size_t)TOK * 128];        // LN2 output
__device__ bf16  g_h   [(size_t)TOK * 512];        // fc1+gelu output
__device__ bf16  g_wqkv[384 * 128];                // Bt layouts: [n][k]
__device__ bf16  g_wproj[128 * 128];
__device__ bf16  g_wfc1 [512 * 128];
__device__ bf16  g_wfc2 [128 * 512];
__device__ float4 g_bm4[229376];                   // bias+mask in C-fragment layout

// ---------------- helpers ----------------
__device__ __forceinline__ void mma16816(float c[4], const uint32_t a[4], const uint32_t b[2]) {
    asm volatile(
        "mma.sync.aligned.m16n8k16.row.col.f32.bf16.bf16.f32 "
        "{%0,%1,%2,%3}, {%4,%5,%6,%7}, {%8,%9}, {%0,%1,%2,%3};\n"
        : "+f"(c[0]), "+f"(c[1]), "+f"(c[2]), "+f"(c[3])
        : "r"(a[0]), "r"(a[1]), "r"(a[2]), "r"(a[3]), "r"(b[0]), "r"(b[1]));
}
__device__ __forceinline__ void ldsm4(uint32_t& r0, uint32_t& r1, uint32_t& r2, uint32_t& r3,
                                      const void* p) {
    uint32_t addr = (uint32_t)__cvta_generic_to_shared(p);
    asm volatile("ldmatrix.sync.aligned.m8n8.x4.shared.b16 {%0,%1,%2,%3}, [%4];\n"
                 : "=r"(r0), "=r"(r1), "=r"(r2), "=r"(r3) : "r"(addr));
}
__device__ __forceinline__ void ldsm4t(uint32_t& r0, uint32_t& r1, uint32_t& r2, uint32_t& r3,
                                       const void* p) {
    uint32_t addr = (uint32_t)__cvta_generic_to_shared(p);
    asm volatile("ldmatrix.sync.aligned.m8n8.x4.trans.shared.b16 {%0,%1,%2,%3}, [%4];\n"
                 : "=r"(r0), "=r"(r1), "=r"(r2), "=r"(r3) : "r"(addr));
}
__device__ __forceinline__ void cpasync16(void* smem_dst, const void* gsrc) {
    uint32_t da = (uint32_t)__cvta_generic_to_shared(smem_dst);
    asm volatile("cp.async.cg.shared.global [%0], [%1], 16;\n" :: "r"(da), "l"(gsrc));
}

// ---------------- prep: weight transpose -> bf16, fragment-layout bias+mask ----------------
__global__ void prep_k(const float* __restrict__ qkv_w, const float* __restrict__ proj_w,
                       const float* __restrict__ fc1_w, const float* __restrict__ fc2_w,
                       const float* __restrict__ rpb,
                       bf16* __restrict__ wq, bf16* __restrict__ wp,
                       bf16* __restrict__ w1, bf16* __restrict__ w2,
                       float* __restrict__ bm4) {
    int m = blockIdx.x * 256 + threadIdx.x;
    if (m < 49152) { int n = m >> 7, k = m & 127; wq[m] = __float2bfloat16(qkv_w[k * 384 + n]); return; }
    m -= 49152;
    if (m < 16384) { int n = m >> 7, k = m & 127; wp[m] = __float2bfloat16(proj_w[k * 128 + n]); return; }
    m -= 16384;
    if (m < 65536) { int n = m >> 7, k = m & 127; w1[m] = __float2bfloat16(fc1_w[k * 512 + n]); return; }
    m -= 65536;
    if (m < 65536) { int n = m >> 9, k = m & 511; w2[m] = __float2bfloat16(fc2_w[k * 128 + n]); return; }
    m -= 65536;
    if (m < 917504) {
        int e = m & 3, lane = (m >> 2) & 31;
        int t = m >> 7;
        int nt = t % 7, q = t / 7;
        int warp = q & 3, hw = q >> 2;
        int head = hw >> 6, w = hw & 63;
        int r = warp * 16 + (lane >> 2) + (e >> 1) * 8;
        int c = nt * 8 + (lane & 3) * 2 + (e & 1);
        float val = -1e30f;
        if (r < 49 && c < 49) {
            int d0 = r / 7 - c / 7 + 6, d1 = r % 7 - c % 7 + 6;
            float bias = rpb[(d0 * 13 + d1) * 4 + head];
            int hi = (w >> 3) * 7 + r / 7, wi = (w & 7) * 7 + r % 7;
            int hj = (w >> 3) * 7 + c / 7, wj = (w & 7) * 7 + c % 7;
            int ri = (hi < 49 ? 0 : (hi < 53 ? 1 : 2)) * 3 + (wi < 49 ? 0 : (wi < 53 ? 1 : 2));
            int rj = (hj < 49 ? 0 : (hj < 53 ? 1 : 2)) * 3 + (wj < 49 ? 0 : (wj < 53 ? 1 : 2));
            val = bias + ((ri != rj) ? -100.0f : 0.0f);
        }
        bm4[m] = val;
    }
}

// ---------------- LayerNorm (optionally with shift+window-partition gather) ----------------
template <bool SHIFTMAP>
__global__ __launch_bounds__(256) void ln_k(const float* __restrict__ X, const float* __restrict__ G,
                                            const float* __restrict__ Bv, bf16* __restrict__ OUT) {
    int gw = (blockIdx.x * 256 + threadIdx.x) >> 5;
    int lane = threadIdx.x & 31;
    if (gw >= TOK) return;
    size_t src;
    if (SHIFTMAP) {
        int bimg = gw / 3136, rem = gw - bimg * 3136;
        int wi = rem / 49, n = rem - wi * 49;
        int sh = (wi >> 3) * 7 + n / 7, sw = (wi & 7) * 7 + n % 7;
        int oh = sh + 3; if (oh >= 56) oh -= 56;
        int ow = sw + 3; if (ow >= 56) ow -= 56;
        src = ((size_t)bimg * 3136 + oh * 56 + ow) * 128;
    } else {
        src = (size_t)gw * 128;
    }
    float4 v = *(const float4*)&X[src + lane * 4];
    float s = v.x + v.y + v.z + v.w;
    float sq = v.x * v.x + v.y * v.y + v.z * v.z + v.w * v.w;
#pragma unroll
    for (int i = 16; i; i >>= 1) {
        s  += __shfl_xor_sync(0xffffffffu, s, i);
        sq += __shfl_xor_sync(0xffffffffu, sq, i);
    }
    float mean = s * 0.0078125f;
    float var = sq * 0.0078125f - mean * mean;
    float rstd = rsqrtf(var + 1e-5f);
    float4 gg = *(const float4*)&G[lane * 4];
    float4 bb = *(const float4*)&Bv[lane * 4];
    float y0 = (v.x - mean) * rstd * gg.x + bb.x;
    float y1 = (v.y - mean) * rstd * gg.y + bb.y;
    float y2 = (v.z - mean) * rstd * gg.z + bb.z;
    float y3 = (v.w - mean) * rstd * gg.w + bb.w;
    __nv_bfloat162* dst = (__nv_bfloat162*)(OUT + (size_t)gw * 128);
    dst[lane * 2]     = __floats2bfloat162_rn(y0, y1);
    dst[lane * 2 + 1] = __floats2bfloat162_rn(y2, y3);
}

// ---------------- GEMM epilogues ----------------
// MODE 0: QKV scatter  1: proj+merge+reverse-shift+residual  2: fc1+GELU  3: fc2+residual
template <int MODE>
__device__ __forceinline__ void epi(int row, int col, float v,
                                    const float* __restrict__ bias, float* __restrict__ outF,
                                    bf16* __restrict__ o1, bf16* __restrict__ o2, bf16* __restrict__ o3,
                                    const float* __restrict__ resid) {
    v += bias[col];
    if (MODE == 0) {
        int three = col >> 7, hc = col & 127, head = hc >> 5, d = hc & 31;
        int win = row / 49, n = row - win * 49;
        size_t idx = ((size_t)(win * 4 + head) * 49 + n) * 32 + d;
        if (three == 0)      o1[idx] = __float2bfloat16(v * 0.17677669529663687f);
        else if (three == 1) o2[idx] = __float2bfloat16(v);
        else                 o3[idx] = __float2bfloat16(v);
    } else if (MODE == 1) {
        int bimg = row / 3136, rem = row - bimg * 3136;
        int wi = rem / 49, n = rem - wi * 49;
        int sh = (wi >> 3) * 7 + n / 7, sw = (wi & 7) * 7 + n % 7;
        int fh = sh + 3; if (fh >= 56) fh -= 56;
        int fw = sw + 3; if (fw >= 56) fw -= 56;
        size_t idx = ((size_t)bimg * 3136 + fh * 56 + fw) * 128 + col;
        outF[idx] = resid[idx] + v;
    } else if (MODE == 2) {
        float gl = 0.5f * v * (1.0f + erff(v * 0.70710678118654752f));
        o1[(size_t)row * 512 + col] = __float2bfloat16(gl);
    } else {
        size_t idx = (size_t)row * 128 + col;
        outF[idx] = resid[idx] + v;
    }
}

// ---------------- GEMM: A[M,K] x Bt[N,K], 128x128 tile, K-chunk 64, cp.async 2-stage ----------
template <int KTOT, int MODE>
__global__ __launch_bounds__(256, 2) void gemm_k(const bf16* __restrict__ A, const bf16* __restrict__ Bt,
                                                 const float* __restrict__ bias,
                                                 float* __restrict__ outF,
                                                 bf16* __restrict__ o1, bf16* __restrict__ o2, bf16* __restrict__ o3,
                                                 const float* __restrict__ resid) {
    // dynamic smem: As[2][128][72], Bs[2][128][72] (pitch 72 -> conflict-free ldmatrix)
    extern __shared__ __align__(16) bf16 sm[];
    bf16* Asm = sm;                    // 2*128*72
    bf16* Bsm = sm + 2 * 128 * 72;
    const int tid = threadIdx.x;
    const int warp = tid >> 5, lane = tid & 31;
    const int wm = warp & 1, wn = warp >> 1;
    const int g = lane >> 2, t4 = lane & 3;
    const int bm0 = blockIdx.x * 128, bn0 = blockIdx.y * 128;
    const int lrow = lane & 15, lcol = (lane >> 4) << 3;

    float acc[4][4][4];
#pragma unroll
    for (int a = 0; a < 4; a++)
#pragma unroll
        for (int b = 0; b < 4; b++)
#pragma unroll
            for (int c = 0; c < 4; c++) acc[a][b][c] = 0.0f;

#define LOAD_STAGE(st, kk)                                                                    \
    do {                                                                                      \
        _Pragma("unroll")                                                                     \
        for (int it = 0; it < 4; ++it) {                                                      \
            int idx = tid + it * 256;                                                         \
            int r = idx >> 3, q = (idx & 7) * 8;                                              \
            cpasync16(&Asm[(st) * 9216 + r * 72 + q], &A[(size_t)(bm0 + r) * KTOT + (kk) + q]);  \
            cpasync16(&Bsm[(st) * 9216 + r * 72 + q], &Bt[(size_t)(bn0 + r) * KTOT + (kk) + q]); \
        }                                                                                     \
        asm volatile("cp.async.commit_group;\n");                                             \
    } while (0)

    constexpr int NCH = KTOT / 64;
    LOAD_STAGE(0, 0);
#pragma unroll
    for (int i = 0; i < NCH; ++i) {
        if (i + 1 < NCH) {
            LOAD_STAGE((i + 1) & 1, (i + 1) * 64);
            asm volatile("cp.async.wait_group 1;\n");
        } else {
            asm volatile("cp.async.wait_group 0;\n");
        }
        __syncthreads();
        const bf16* As = Asm + (i & 1) * 9216;
        const bf16* Bs = Bsm + (i & 1) * 9216;
#pragma unroll
        for (int ks = 0; ks < 4; ++ks) {
            const int k0 = ks * 16;
            uint32_t af[4][4];
#pragma unroll
            for (int mt = 0; mt < 4; ++mt) {
                int m0 = wm * 64 + mt * 16;
                ldsm4(af[mt][0], af[mt][1], af[mt][2], af[mt][3],
                      &As[(m0 + lrow) * 72 + k0 + lcol]);
            }
            uint32_t bfr[4][2];
#pragma unroll
            for (int np = 0; np < 2; ++np) {
                int n0 = wn * 32 + np * 16;
                uint32_t r0, r1, r2, r3;
                ldsm4(r0, r1, r2, r3, &Bs[(n0 + lrow) * 72 + k0 + lcol]);
                bfr[np * 2][0] = r0; bfr[np * 2 + 1][0] = r1;
                bfr[np * 2][1] = r2; bfr[np * 2 + 1][1] = r3;
            }
#pragma unroll
            for (int mt = 0; mt < 4; ++mt)
#pragma unroll
                for (int nt = 0; nt < 4; ++nt)
                    mma16816(acc[mt][nt], af[mt], bfr[nt]);
        }
        __syncthreads();
    }
#undef LOAD_STAGE
#pragma unroll
    for (int mt = 0; mt < 4; ++mt) {
#pragma unroll
        for (int nt = 0; nt < 4; ++nt) {
            int row0 = bm0 + wm * 64 + mt * 16 + g;
            int col0 = bn0 + wn * 32 + nt * 8 + 2 * t4;
            epi<MODE>(row0,     col0,     acc[mt][nt][0], bias, outF, o1, o2, o3, resid);
            epi<MODE>(row0,     col0 + 1, acc[mt][nt][1], bias, outF, o1, o2, o3, resid);
            epi<MODE>(row0 + 8, col0,     acc[mt][nt][2], bias, outF, o1, o2, o3, resid);
            epi<MODE>(row0 + 8, col0 + 1, acc[mt][nt][3], bias, outF, o1, o2, o3, resid);
        }
    }
}

// ---------------- attention: one block per (window, head), ldmatrix everywhere --------------
__global__ __launch_bounds__(128) void attn_k(const bf16* __restrict__ Q, const bf16* __restrict__ K,
                                              const bf16* __restrict__ V,
                                              const float4* __restrict__ bm4,
                                              bf16* __restrict__ O) {
    __shared__ __align__(16) bf16 qs[64][40];
    __shared__ __align__(16) bf16 ks[64][40];
    __shared__ __align__(16) bf16 vs[64][40];

    const int tid = threadIdx.x, warp = tid >> 5, lane = tid & 31;
    const int g = lane >> 2, t4 = lane & 3;
    const int lrow = lane & 15, lcol = (lane >> 4) << 3;
    const int bx = blockIdx.x, win = bx >> 2, head = bx & 3, wimg = win & 63;
    const bf16* qg = Q + (size_t)bx * 1568;
    const bf16* kg = K + (size_t)bx * 1568;
    const bf16* vg = V + (size_t)bx * 1568;

    // prefetch bias+mask fragments (coalesced float4, fragment layout)
    const float4* bmq = bm4 + (size_t)(((head * 64 + wimg) * 4 + warp) * 7) * 32;
    float4 bmv[7];
#pragma unroll
    for (int nt = 0; nt < 7; nt++) bmv[nt] = __ldg(&bmq[nt * 32 + lane]);

    // fill q/k/v smem with 16B loads; rows 49..63 zero
    const uint4 zero4 = make_uint4(0u, 0u, 0u, 0u);
#pragma unroll
    for (int it = 0; it < 2; ++it) {
        int idx = tid + it * 128;
        int row = idx >> 2, col = (idx & 3) * 8;
        bool vld = row < 49;
        uint4 a = vld ? *(const uint4*)&qg[row * 32 + col] : zero4;
        uint4 b = vld ? *(const uint4*)&kg[row * 32 + col] : zero4;
        uint4 c = vld ? *(const uint4*)&vg[row * 32 + col] : zero4;
        *(uint4*)&qs[row][col] = a;
        *(uint4*)&ks[row][col] = b;
        *(uint4*)&vs[row][col] = c;
    }
    __syncthreads();

    // ---- S = q @ k^T (q pre-scaled), each warp: rows m0..m0+15 ----
    const int m0 = warp * 16;
    float sacc[7][4];
#pragma unroll
    for (int nt = 0; nt < 7; nt++) { sacc[nt][0] = sacc[nt][1] = sacc[nt][2] = sacc[nt][3] = 0.f; }
#pragma unroll
    for (int kq = 0; kq < 2; ++kq) {
        const int k0 = kq * 16;
        uint32_t af[4];
        ldsm4(af[0], af[1], af[2], af[3], &qs[m0 + lrow][k0 + lcol]);
        uint32_t kb[4][4];
#pragma unroll
        for (int ntp = 0; ntp < 4; ++ntp)
            ldsm4(kb[ntp][0], kb[ntp][1], kb[ntp][2], kb[ntp][3],
                  &ks[ntp * 16 + lrow][k0 + lcol]);
#pragma unroll
        for (int nt = 0; nt < 7; nt++) {
            uint32_t bb[2];
            bb[0] = (nt & 1) ? kb[nt >> 1][1] : kb[nt >> 1][0];
            bb[1] = (nt & 1) ? kb[nt >> 1][3] : kb[nt >> 1][2];
            mma16816(sacc[nt], af, bb);
        }
    }

    // ---- bias+mask add, register softmax (rows r1=m0+g, r2=m0+g+8) ----
    float l1[7][2], l2[7][2];
#pragma unroll
    for (int nt = 0; nt < 7; nt++) {
        l1[nt][0] = sacc[nt][0] + bmv[nt].x;
        l1[nt][1] = sacc[nt][1] + bmv[nt].y;
        l2[nt][0] = sacc[nt][2] + bmv[nt].z;
        l2[nt][1] = sacc[nt][3] + bmv[nt].w;
    }
    float mx1 = -1e30f, mx2 = -1e30f;
#pragma unroll
    for (int nt = 0; nt < 7; nt++) {
        mx1 = fmaxf(mx1, fmaxf(l1[nt][0], l1[nt][1]));
        mx2 = fmaxf(mx2, fmaxf(l2[nt][0], l2[nt][1]));
    }
    mx1 = fmaxf(mx1, __shfl_xor_sync(0xffffffffu, mx1, 1));
    mx1 = fmaxf(mx1, __shfl_xor_sync(0xffffffffu, mx1, 2));
    mx2 = fmaxf(mx2, __shfl_xor_sync(0xffffffffu, mx2, 1));
    mx2 = fmaxf(mx2, __shfl_xor_sync(0xffffffffu, mx2, 2));
    float sm1 = 0.f, sm2 = 0.f;
#pragma unroll
    for (int nt = 0; nt < 7; nt++) {
#pragma unroll
        for (int e = 0; e < 2; e++) {
            l1[nt][e] = __expf(l1[nt][e] - mx1);
            l2[nt][e] = __expf(l2[nt][e] - mx2);
            sm1 += l1[nt][e];
            sm2 += l2[nt][e];
        }
    }
    sm1 += __shfl_xor_sync(0xffffffffu, sm1, 1);
    sm1 += __shfl_xor_sync(0xffffffffu, sm1, 2);
    sm2 += __shfl_xor_sync(0xffffffffu, sm2, 1);
    sm2 += __shfl_xor_sync(0xffffffffu, sm2, 2);
    const float inv1 = 1.0f / sm1, inv2 = 1.0f / sm2;
    uint32_t pk1[7], pk2[7];
#pragma unroll
    for (int nt = 0; nt < 7; nt++) {
        __nv_bfloat162 p1 = __floats2bfloat162_rn(l1[nt][0] * inv1, l1[nt][1] * inv1);
        __nv_bfloat162 p2 = __floats2bfloat162_rn(l2[nt][0] * inv2, l2[nt][1] * inv2);
        pk1[nt] = *(uint32_t*)&p1;
        pk2[nt] = *(uint32_t*)&p2;
    }

    // ---- O = P @ V (P fragments == softmaxed S fragments; V via ldmatrix.trans) ----
    float oacc[4][4];
#pragma unroll
    for (int nt = 0; nt < 4; nt++) { oacc[nt][0] = oacc[nt][1] = oacc[nt][2] = oacc[nt][3] = 0.f; }
#pragma unroll
    for (int kt = 0; kt < 4; ++kt) {
        const int k0 = kt * 16;
        uint32_t af[4];
        af[0] = pk1[2 * kt];
        af[1] = pk2[2 * kt];
        af[2] = (kt < 3) ? pk1[2 * kt + 1] : 0u;
        af[3] = (kt < 3) ? pk2[2 * kt + 1] : 0u;
        uint32_t v0[4], v1[4];
        ldsm4t(v0[0], v0[1], v0[2], v0[3], &vs[k0 + lrow][lcol]);       // n = 0..15
        ldsm4t(v1[0], v1[1], v1[2], v1[3], &vs[k0 + lrow][16 + lcol]);  // n = 16..31
        { uint32_t bb[2] = { v0[0], v0[1] }; mma16816(oacc[0], af, bb); }
        { uint32_t bb[2] = { v0[2], v0[3] }; mma16816(oacc[1], af, bb); }
        { uint32_t bb[2] = { v1[0], v1[1] }; mma16816(oacc[2], af, bb); }
        { uint32_t bb[2] = { v1[2], v1[3] }; mma16816(oacc[3], af, bb); }
    }
    const size_t obase = (size_t)win * 49;
    const int r1 = m0 + g, r2 = m0 + g + 8;
#pragma unroll
    for (int nt = 0; nt < 4; nt++) {
        int col = head * 32 + nt * 8 + 2 * t4;
        if (r1 < 49)
            *(__nv_bfloat162*)&O[(obase + r1) * 128 + col] = __floats2bfloat162_rn(oacc[nt][0], oacc[nt][1]);
        if (r2 < 49)
            *(__nv_bfloat162*)&O[(obase + r2) * 128 + col] = __floats2bfloat162_rn(oacc[nt][2], oacc[nt][3]);
    }
}

// ---------------- host ----------------
extern "C" void kernel_launch(void* const* d_in, const int* in_sizes, int n_in,
                              void* d_out, int out_size) {
    const float* x      = (const float*)d_in[0];
    const float* n1g    = (const float*)d_in[1];
    const float* n1b    = (const float*)d_in[2];
    const float* qkv_w  = (const float*)d_in[3];
    const float* qkv_b  = (const float*)d_in[4];
    const float* proj_w = (const float*)d_in[5];
    const float* proj_b = (const float*)d_in[6];
    const float* rpb    = (const float*)d_in[7];
    const float* n2g    = (const float*)d_in[8];
    const float* n2b    = (const float*)d_in[9];
    const float* fc1_w  = (const float*)d_in[10];
    const float* fc1_b  = (const float*)d_in[11];
    const float* fc2_w  = (const float*)d_in[12];
    const float* fc2_b  = (const float*)d_in[13];
    float* out = (float*)d_out;

    void* p;
    cudaGetSymbolAddress(&p, g_hw);    bf16* hw = (bf16*)p;
    cudaGetSymbolAddress(&p, g_q);     bf16* qb = (bf16*)p;
    cudaGetSymbolAddress(&p, g_k);     bf16* kb = (bf16*)p;
    cudaGetSymbolAddress(&p, g_v);     bf16* vb = (bf16*)p;
    cudaGetSymbolAddress(&p, g_o);     bf16* ob = (bf16*)p;
    cudaGetSymbolAddress(&p, g_x1);    float* x1 = (float*)p;
    cudaGetSymbolAddress(&p, g_t);     bf16* tb = (bf16*)p;
    cudaGetSymbolAddress(&p, g_h);     bf16* hb = (bf16*)p;
    cudaGetSymbolAddress(&p, g_wqkv);  bf16* wq = (bf16*)p;
    cudaGetSymbolAddress(&p, g_wproj); bf16* wp = (bf16*)p;
    cudaGetSymbolAddress(&p, g_wfc1);  bf16* w1 = (bf16*)p;
    cudaGetSymbolAddress(&p, g_wfc2);  bf16* w2 = (bf16*)p;
    cudaGetSymbolAddress(&p, g_bm4);   float* bmp = (float*)p;

    const int GSM = 2 * 128 * 72 * 2 * 2;   // 73728 bytes dynamic smem
    cudaFuncSetAttribute(gemm_k<128, 0>, cudaFuncAttributeMaxDynamicSharedMemorySize, GSM);
    cudaFuncSetAttribute(gemm_k<128, 1>, cudaFuncAttributeMaxDynamicSharedMemorySize, GSM);
    cudaFuncSetAttribute(gemm_k<128, 2>, cudaFuncAttributeMaxDynamicSharedMemorySize, GSM);
    cudaFuncSetAttribute(gemm_k<512, 3>, cudaFuncAttributeMaxDynamicSharedMemorySize, GSM);

    prep_k<<<4352, 256>>>(qkv_w, proj_w, fc1_w, fc2_w, rpb, wq, wp, w1, w2, bmp);
    ln_k<true><<<12544, 256>>>(x, n1g, n1b, hw);
    gemm_k<128, 0><<<dim3(784, 3), 256, GSM>>>(hw, wq, qkv_b, nullptr, qb, kb, vb, nullptr);
    attn_k<<<8192, 128>>>(qb, kb, vb, (const float4*)bmp, ob);
    gemm_k<128, 1><<<dim3(784, 1), 256, GSM>>>(ob, wp, proj_b, x1, nullptr, nullptr, nullptr, x);
    ln_k<false><<<12544, 256>>>(x1, n2g, n2b, tb);
    gemm_k<128, 2><<<dim3(784, 4), 256, GSM>>>(tb, w1, fc1_b, nullptr, hb, nullptr, nullptr, nullptr);
    gemm_k<512, 3><<<dim3(784, 1), 256, GSM>>>(hb, w2, fc2_b, out, nullptr, nullptr, nullptr, x1);
}